// round 1
// baseline (speedup 1.0000x reference)
#include <cuda_runtime.h>
#include <cstdint>

#define T_TOK 8192
#define D_DIM 1024
#define E_EXP 8
#define F_DIM 2048
#define NSLOT (2 * T_TOK)

// ---------------- device-global scratch (allocation-free rule) ----------------
__device__ int   g_cnt[E_EXP];
__device__ int   g_list[E_EXP * T_TOK];        // slot ids (2t+k) grouped by expert
__device__ float g_probs[NSLOT];               // gate prob per slot
__device__ float g_H[(size_t)NSLOT * F_DIM];   // 134 MB intermediate
__device__ float g_Y[(size_t)NSLOT * D_DIM];   // 67 MB expert outputs

// ---------------- init: zero routing counters (every graph replay) ------------
__global__ void init_kernel() {
    if (threadIdx.x < E_EXP) g_cnt[threadIdx.x] = 0;
}

// ---------------- gating: logits, top-2, softmax, routing lists ---------------
__global__ void __launch_bounds__(256) gate_kernel(const float* __restrict__ x,
                                                   const float* __restrict__ wg) {
    __shared__ float swg[E_EXP][D_DIM];  // transposed [e][d], 32 KB
    int tid = threadIdx.x;
    for (int i = tid; i < D_DIM * E_EXP; i += 256) {
        int d = i >> 3, e = i & 7;
        swg[e][d] = wg[i];
    }
    __syncthreads();

    int warp = tid >> 5, lane = tid & 31;
    int t = blockIdx.x * 8 + warp;
    const float* xr = x + (size_t)t * D_DIM;

    float acc[E_EXP];
#pragma unroll
    for (int e = 0; e < E_EXP; e++) acc[e] = 0.f;

    for (int d = lane; d < D_DIM; d += 32) {
        float xv = xr[d];
#pragma unroll
        for (int e = 0; e < E_EXP; e++) acc[e] = fmaf(xv, swg[e][d], acc[e]);
    }
#pragma unroll
    for (int e = 0; e < E_EXP; e++) {
#pragma unroll
        for (int o = 16; o > 0; o >>= 1)
            acc[e] += __shfl_xor_sync(0xffffffffu, acc[e], o);
    }

    if (lane == 0) {
        // top-1: strict > keeps lowest index on ties (jax top_k semantics)
        int e0 = 0; float l0 = acc[0];
#pragma unroll
        for (int e = 1; e < E_EXP; e++) if (acc[e] > l0) { l0 = acc[e]; e0 = e; }
        // top-2 excluding e0
        int e1 = -1; float l1 = -3.0e38f;
#pragma unroll
        for (int e = 0; e < E_EXP; e++) {
            if (e == e0) continue;
            if (acc[e] > l1) { l1 = acc[e]; e1 = e; }
        }
        // softmax over the selected pair (l0 >= l1)
        float ex = __expf(l1 - l0);
        float inv = 1.f / (1.f + ex);
        g_probs[2 * t]     = inv;
        g_probs[2 * t + 1] = ex * inv;

        int p0 = atomicAdd(&g_cnt[e0], 1);
        g_list[e0 * T_TOK + p0] = 2 * t;
        int p1 = atomicAdd(&g_cnt[e1], 1);
        g_list[e1 * T_TOK + p1] = 2 * t + 1;
    }
}

// ---------------- GEMM1: H[slot] = silu(x@w1_e) * (x@w3_e) --------------------
// 64x64x16 tiles, 256 threads, 4x4 per thread for each of C1/C3.
__global__ void __launch_bounds__(256) gemm1_kernel(const float* __restrict__ x,
                                                    const float* __restrict__ w1,
                                                    const float* __restrict__ w3) {
    int e   = blockIdx.z;
    int n_e = g_cnt[e];
    int m0  = blockIdx.x * 64;
    if (m0 >= n_e) return;
    int f0  = blockIdx.y * 64;

    __shared__ float As[16][68];   // [k][m], padded stride
    __shared__ float B1s[16][64];  // [k][n]
    __shared__ float B3s[16][64];
    __shared__ int   slots[64];

    int tid = threadIdx.x;
    if (tid < 64) {
        int m = m0 + tid;
        slots[tid] = (m < n_e) ? g_list[e * T_TOK + m] : g_list[e * T_TOK];
    }
    __syncthreads();

    const float* W1 = w1 + (size_t)e * D_DIM * F_DIM + f0;
    const float* W3 = w3 + (size_t)e * D_DIM * F_DIM + f0;

    int am = tid >> 2;               // 0..63 (row within tile)
    int ak = (tid & 3) * 4;          // 0,4,8,12
    const float* arow = x + (size_t)(slots[am] >> 1) * D_DIM + ak;
    int bk = tid >> 4;               // 0..15
    int bn = (tid & 15) * 4;
    int tx = tid & 15, ty = tid >> 4;

    float c1[4][4] = {}, c3[4][4] = {};

    for (int k0 = 0; k0 < D_DIM; k0 += 16) {
        float4 av = *(const float4*)(arow + k0);
        As[ak + 0][am] = av.x; As[ak + 1][am] = av.y;
        As[ak + 2][am] = av.z; As[ak + 3][am] = av.w;
        *(float4*)&B1s[bk][bn] = *(const float4*)(W1 + (size_t)(k0 + bk) * F_DIM + bn);
        *(float4*)&B3s[bk][bn] = *(const float4*)(W3 + (size_t)(k0 + bk) * F_DIM + bn);
        __syncthreads();

#pragma unroll
        for (int k = 0; k < 16; k++) {
            float4 a  = *(const float4*)&As[k][ty * 4];
            float4 b1 = *(const float4*)&B1s[k][tx * 4];
            float4 b3 = *(const float4*)&B3s[k][tx * 4];
            float aa[4]  = {a.x, a.y, a.z, a.w};
            float v1[4]  = {b1.x, b1.y, b1.z, b1.w};
            float v3[4]  = {b3.x, b3.y, b3.z, b3.w};
#pragma unroll
            for (int i = 0; i < 4; i++)
#pragma unroll
                for (int j = 0; j < 4; j++) {
                    c1[i][j] = fmaf(aa[i], v1[j], c1[i][j]);
                    c3[i][j] = fmaf(aa[i], v3[j], c3[i][j]);
                }
        }
        __syncthreads();
    }

#pragma unroll
    for (int i = 0; i < 4; i++) {
        int m = ty * 4 + i;
        if (m0 + m < n_e) {
            int slot = slots[m];
            float* hr = g_H + (size_t)slot * F_DIM + f0 + tx * 4;
#pragma unroll
            for (int j = 0; j < 4; j++) {
                float v = c1[i][j];
                float s = v / (1.f + __expf(-v));   // silu
                hr[j] = s * c3[i][j];
            }
        }
    }
}

// ---------------- GEMM2: Y[slot] = H[slot] @ w2_e -----------------------------
__global__ void __launch_bounds__(256) gemm2_kernel(const float* __restrict__ w2) {
    int e   = blockIdx.z;
    int n_e = g_cnt[e];
    int m0  = blockIdx.x * 64;
    if (m0 >= n_e) return;
    int n0  = blockIdx.y * 64;

    __shared__ float As[16][68];
    __shared__ float Bs[16][64];
    __shared__ int   slots[64];

    int tid = threadIdx.x;
    if (tid < 64) {
        int m = m0 + tid;
        slots[tid] = (m < n_e) ? g_list[e * T_TOK + m] : g_list[e * T_TOK];
    }
    __syncthreads();

    const float* W2 = w2 + (size_t)e * F_DIM * D_DIM + n0;

    int am = tid >> 2;
    int ak = (tid & 3) * 4;
    const float* arow = g_H + (size_t)slots[am] * F_DIM + ak;
    int bk = tid >> 4;
    int bn = (tid & 15) * 4;
    int tx = tid & 15, ty = tid >> 4;

    float c[4][4] = {};

    for (int k0 = 0; k0 < F_DIM; k0 += 16) {
        float4 av = *(const float4*)(arow + k0);
        As[ak + 0][am] = av.x; As[ak + 1][am] = av.y;
        As[ak + 2][am] = av.z; As[ak + 3][am] = av.w;
        *(float4*)&Bs[bk][bn] = *(const float4*)(W2 + (size_t)(k0 + bk) * D_DIM + bn);
        __syncthreads();

#pragma unroll
        for (int k = 0; k < 16; k++) {
            float4 a = *(const float4*)&As[k][ty * 4];
            float4 b = *(const float4*)&Bs[k][tx * 4];
            float aa[4] = {a.x, a.y, a.z, a.w};
            float bb[4] = {b.x, b.y, b.z, b.w};
#pragma unroll
            for (int i = 0; i < 4; i++)
#pragma unroll
                for (int j = 0; j < 4; j++)
                    c[i][j] = fmaf(aa[i], bb[j], c[i][j]);
        }
        __syncthreads();
    }

#pragma unroll
    for (int i = 0; i < 4; i++) {
        int m = ty * 4 + i;
        if (m0 + m < n_e) {
            float* yr = g_Y + (size_t)slots[m] * D_DIM + n0 + tx * 4;
#pragma unroll
            for (int j = 0; j < 4; j++) yr[j] = c[i][j];
        }
    }
}

// ---------------- combine: out[t] = p0*Y[2t] + p1*Y[2t+1] ---------------------
__global__ void __launch_bounds__(256) combine_kernel(float* __restrict__ out) {
    int idx = blockIdx.x * 256 + threadIdx.x;            // over T*D/4
    int t   = idx / (D_DIM / 4);
    int d4  = idx % (D_DIM / 4);
    float p0 = g_probs[2 * t], p1 = g_probs[2 * t + 1];
    const float4* y0 = (const float4*)(g_Y + (size_t)(2 * t) * D_DIM) + d4;
    const float4* y1 = (const float4*)(g_Y + (size_t)(2 * t + 1) * D_DIM) + d4;
    float4 a = *y0, b = *y1, o;
    o.x = p0 * a.x + p1 * b.x;
    o.y = p0 * a.y + p1 * b.y;
    o.z = p0 * a.z + p1 * b.z;
    o.w = p0 * a.w + p1 * b.w;
    *((float4*)(out + (size_t)t * D_DIM) + d4) = o;
}

// ---------------- launch ------------------------------------------------------
extern "C" void kernel_launch(void* const* d_in, const int* in_sizes, int n_in,
                              void* d_out, int out_size) {
    const float* x  = (const float*)d_in[0];
    const float* wg = (const float*)d_in[1];
    const float* w1 = (const float*)d_in[2];
    const float* w3 = (const float*)d_in[3];
    const float* w2 = (const float*)d_in[4];
    float* out = (float*)d_out;

    init_kernel<<<1, 32>>>();
    gate_kernel<<<T_TOK / 8, 256>>>(x, wg);

    dim3 g1(T_TOK / 64 * 2 / 2, F_DIM / 64, E_EXP);   // 128 m-tiles (worst case n_e = T)
    gemm1_kernel<<<dim3(128, F_DIM / 64, E_EXP), 256>>>(x, w1, w3);
    gemm2_kernel<<<dim3(128, D_DIM / 64, E_EXP), 256>>>(w2);

    combine_kernel<<<(T_TOK * D_DIM / 4) / 256, 256>>>(out);
}

// round 3
// speedup vs baseline: 3.7627x; 3.7627x over previous
#include <cuda_runtime.h>
#include <cstdint>

#define T_TOK 8192
#define D_DIM 1024
#define E_EXP 8
#define F_DIM 2048
#define NSLOT (2 * T_TOK)

// ---------------- device-global scratch ----------------
__device__ int   g_cnt[E_EXP];
__device__ int   g_list[E_EXP * T_TOK];
__device__ float g_probs[NSLOT];
__device__ float g_H[(size_t)NSLOT * F_DIM];      // rounded-to-tf32 intermediate
__device__ float g_Y[(size_t)NSLOT * D_DIM];
__device__ float g_xr[(size_t)T_TOK * D_DIM];     // tf32-rounded copies
__device__ float g_w1r[(size_t)E_EXP * D_DIM * F_DIM];
__device__ float g_w3r[(size_t)E_EXP * D_DIM * F_DIM];
__device__ float g_w2r[(size_t)E_EXP * F_DIM * D_DIM];

// ---------------- helpers ----------------
__device__ __forceinline__ uint32_t smem_u32(const void* p) {
    uint32_t a;
    asm("{ .reg .u64 t; cvta.to.shared.u64 t, %1; cvt.u32.u64 %0, t; }" : "=r"(a) : "l"(p));
    return a;
}
__device__ __forceinline__ float to_tf32(float x) {
    uint32_t r;
    asm("cvt.rna.tf32.f32 %0, %1;" : "=r"(r) : "f"(x));
    return __uint_as_float(r);
}
#define CP16(dst, src) asm volatile("cp.async.cg.shared.global [%0], [%1], 16;" :: "r"(dst), "l"(src))
#define CP_COMMIT()    asm volatile("cp.async.commit_group;")
#define CP_WAIT1()     asm volatile("cp.async.wait_group 1;")

#define MMA_TF32(c, a, b)                                                          \
    asm volatile("mma.sync.aligned.m16n8k8.row.col.f32.tf32.tf32.f32 "             \
                 "{%0,%1,%2,%3}, {%4,%5,%6,%7}, {%8,%9}, {%0,%1,%2,%3};"           \
                 : "+f"((c)[0]), "+f"((c)[1]), "+f"((c)[2]), "+f"((c)[3])          \
                 : "r"((a)[0]), "r"((a)[1]), "r"((a)[2]), "r"((a)[3]),             \
                   "r"((b)[0]), "r"((b)[1]))

// smem strides (floats): A rows padded to 36 (144B), B rows padded to 136 (544B)
#define AST 36
#define BST 136
#define A_BYTES (128 * AST * 4)   // 18432
#define B_BYTES (32 * BST * 4)    // 17408

// ---------------- init ----------------
__global__ void init_kernel() {
    if (threadIdx.x < E_EXP) g_cnt[threadIdx.x] = 0;
}

// ---------------- tf32 pre-round: out[i] = rna_tf32(in[i]) ----------------
__global__ void __launch_bounds__(256) round_kernel(const float4* __restrict__ in,
                                                    float4* __restrict__ out, int n4) {
    int i = blockIdx.x * 256 + threadIdx.x;
    int stride = gridDim.x * 256;
    for (; i < n4; i += stride) {
        float4 v = in[i];
        v.x = to_tf32(v.x); v.y = to_tf32(v.y);
        v.z = to_tf32(v.z); v.w = to_tf32(v.w);
        out[i] = v;
    }
}

// ---------------- gating (proven in R1) ----------------
__global__ void __launch_bounds__(256) gate_kernel(const float* __restrict__ x,
                                                   const float* __restrict__ wg) {
    __shared__ float swg[E_EXP][D_DIM];
    int tid = threadIdx.x;
    for (int i = tid; i < D_DIM * E_EXP; i += 256) {
        int d = i >> 3, e = i & 7;
        swg[e][d] = wg[i];
    }
    __syncthreads();

    int warp = tid >> 5, lane = tid & 31;
    int t = blockIdx.x * 8 + warp;
    const float* xr = x + (size_t)t * D_DIM;

    float acc[E_EXP];
#pragma unroll
    for (int e = 0; e < E_EXP; e++) acc[e] = 0.f;
    for (int d = lane; d < D_DIM; d += 32) {
        float xv = xr[d];
#pragma unroll
        for (int e = 0; e < E_EXP; e++) acc[e] = fmaf(xv, swg[e][d], acc[e]);
    }
#pragma unroll
    for (int e = 0; e < E_EXP; e++)
#pragma unroll
        for (int o = 16; o > 0; o >>= 1)
            acc[e] += __shfl_xor_sync(0xffffffffu, acc[e], o);

    if (lane == 0) {
        int e0 = 0; float l0 = acc[0];
#pragma unroll
        for (int e = 1; e < E_EXP; e++) if (acc[e] > l0) { l0 = acc[e]; e0 = e; }
        int e1 = -1; float l1 = -3.0e38f;
#pragma unroll
        for (int e = 0; e < E_EXP; e++) {
            if (e == e0) continue;
            if (acc[e] > l1) { l1 = acc[e]; e1 = e; }
        }
        float ex  = __expf(l1 - l0);
        float inv = 1.f / (1.f + ex);
        g_probs[2 * t]     = inv;
        g_probs[2 * t + 1] = ex * inv;
        int p0 = atomicAdd(&g_cnt[e0], 1);
        g_list[e0 * T_TOK + p0] = 2 * t;
        int p1 = atomicAdd(&g_cnt[e1], 1);
        g_list[e1 * T_TOK + p1] = 2 * t + 1;
    }
}

// ======================= GEMM1: H = silu(x@w1) * (x@w3) =======================
// CTA 128x128, 8 warps (2m x 4n), warp tile 64x32, K chunks of 32, 3-stage cp.async.
// Dyn smem: slots @0, stages @1024, stage = A(18432) + B1(17408) + B3(17408) = 53248.
__global__ void __launch_bounds__(256, 1) gemm1_kernel(const float* __restrict__ xr,
                                                       const float* __restrict__ w1,
                                                       const float* __restrict__ w3) {
    int e   = blockIdx.z;
    int n_e = g_cnt[e];
    int m0  = blockIdx.x * 128;
    if (m0 >= n_e) return;
    int f0  = blockIdx.y * 128;

    extern __shared__ char smem[];
    int* slots = (int*)smem;
    uint32_t sb = smem_u32(smem);
    int tid = threadIdx.x, wid = tid >> 5, lane = tid & 31;

    if (tid < 128) {
        int m = m0 + tid;
        slots[tid] = g_list[e * T_TOK + (m < n_e ? m : m0)];
    }
    __syncthreads();

    const float* W1 = w1 + (size_t)e * D_DIM * F_DIM + f0;
    const float* W3 = w3 + (size_t)e * D_DIM * F_DIM + f0;

    // ---- cp.async producer: chunk ci -> stage s ----
    auto issue = [&](int ci, int s) {
        int k0 = ci * 32;
        uint32_t base = sb + 1024 + s * (A_BYTES + 2 * B_BYTES);
#pragma unroll
        for (int it = 0; it < 4; it++) {               // A: 128 rows x 8 quads
            int idx = it * 256 + tid;
            int row = idx >> 3, kq = idx & 7;
            const float* src = xr + (size_t)(slots[row] >> 1) * D_DIM + k0 + kq * 4;
            CP16(base + row * 144 + kq * 16, src);
        }
        uint32_t b1b = base + A_BYTES, b3b = base + A_BYTES + B_BYTES;
#pragma unroll
        for (int it = 0; it < 4; it++) {               // B: 32 k-rows x 32 quads
            int idx = it * 256 + tid;
            int kr = idx >> 5, nq = idx & 31;
            size_t off = (size_t)(k0 + kr) * F_DIM + nq * 4;
            CP16(b1b + kr * 544 + nq * 16, W1 + off);
            CP16(b3b + kr * 544 + nq * 16, W3 + off);
        }
        CP_COMMIT();
    };

    issue(0, 0);
    issue(1, 1);

    int g = lane >> 2, t = lane & 3;
    int m0w = (wid & 1) * 64, n0w = (wid >> 1) * 32;

    float c1[4][4][4], c3[4][4][4];
#pragma unroll
    for (int a = 0; a < 4; a++)
#pragma unroll
        for (int b = 0; b < 4; b++)
#pragma unroll
            for (int r = 0; r < 4; r++) { c1[a][b][r] = 0.f; c3[a][b][r] = 0.f; }

    const int NCH = D_DIM / 32;  // 32
    int cur = 0, ibuf = 2;
    for (int ci = 0; ci < NCH; ci++) {
        CP_WAIT1();
        __syncthreads();
        if (ci + 2 < NCH) issue(ci + 2, ibuf); else CP_COMMIT();
        if (++ibuf == 3) ibuf = 0;

        const float* As  = (const float*)(smem + 1024 + cur * (A_BYTES + 2 * B_BYTES));
        const float* B1s = As + A_BYTES / 4;
        const float* B3s = As + (A_BYTES + B_BYTES) / 4;
        if (++cur == 3) cur = 0;

#pragma unroll
        for (int kk = 0; kk < 4; kk++) {
            uint32_t af[4][4], b1f[4][2], b3f[4][2];
#pragma unroll
            for (int mf = 0; mf < 4; mf++) {
                const float* ap = As + (m0w + mf * 16 + g) * AST + kk * 8 + t;
                af[mf][0] = __float_as_uint(ap[0]);
                af[mf][1] = __float_as_uint(ap[8 * AST]);
                af[mf][2] = __float_as_uint(ap[4]);
                af[mf][3] = __float_as_uint(ap[8 * AST + 4]);
            }
#pragma unroll
            for (int nf = 0; nf < 4; nf++) {
                const float* bp = B1s + (kk * 8 + t) * BST + n0w + nf * 8 + g;
                b1f[nf][0] = __float_as_uint(bp[0]);
                b1f[nf][1] = __float_as_uint(bp[4 * BST]);
                const float* cp = B3s + (kk * 8 + t) * BST + n0w + nf * 8 + g;
                b3f[nf][0] = __float_as_uint(cp[0]);
                b3f[nf][1] = __float_as_uint(cp[4 * BST]);
            }
#pragma unroll
            for (int mf = 0; mf < 4; mf++)
#pragma unroll
                for (int nf = 0; nf < 4; nf++) {
                    MMA_TF32(c1[mf][nf], af[mf], b1f[nf]);
                    MMA_TF32(c3[mf][nf], af[mf], b3f[nf]);
                }
        }
    }

    // ---- epilogue: H = rna_tf32(silu(c1) * c3) ----
#pragma unroll
    for (int mf = 0; mf < 4; mf++) {
#pragma unroll
        for (int half = 0; half < 2; half++) {
            int row = m0w + mf * 16 + g + 8 * half;
            if (m0 + row >= n_e) continue;
            float* hp = g_H + (size_t)slots[row] * F_DIM + f0;
#pragma unroll
            for (int nf = 0; nf < 4; nf++) {
                float v0 = c1[mf][nf][2 * half + 0];
                float v1 = c1[mf][nf][2 * half + 1];
                float2 o;
                o.x = to_tf32((v0 / (1.f + __expf(-v0))) * c3[mf][nf][2 * half + 0]);
                o.y = to_tf32((v1 / (1.f + __expf(-v1))) * c3[mf][nf][2 * half + 1]);
                *(float2*)(hp + n0w + nf * 8 + 2 * t) = o;
            }
        }
    }
}

// ======================= GEMM2: Y = H @ w2 =======================
// Same tiling, K = 2048 in 64 chunks, stage = A(18432) + B(17408) = 35840, 3 stages.
__global__ void __launch_bounds__(256, 2) gemm2_kernel(const float* __restrict__ w2) {
    int e   = blockIdx.z;
    int n_e = g_cnt[e];
    int m0  = blockIdx.x * 128;
    if (m0 >= n_e) return;
    int n0  = blockIdx.y * 128;

    extern __shared__ char smem[];
    int* slots = (int*)smem;
    uint32_t sb = smem_u32(smem);
    int tid = threadIdx.x, wid = tid >> 5, lane = tid & 31;

    if (tid < 128) {
        int m = m0 + tid;
        slots[tid] = g_list[e * T_TOK + (m < n_e ? m : m0)];
    }
    __syncthreads();

    const float* W2 = w2 + (size_t)e * F_DIM * D_DIM + n0;

    auto issue = [&](int ci, int s) {
        int k0 = ci * 32;
        uint32_t base = sb + 1024 + s * (A_BYTES + B_BYTES);
#pragma unroll
        for (int it = 0; it < 4; it++) {
            int idx = it * 256 + tid;
            int row = idx >> 3, kq = idx & 7;
            const float* src = g_H + (size_t)slots[row] * F_DIM + k0 + kq * 4;
            CP16(base + row * 144 + kq * 16, src);
        }
        uint32_t bb = base + A_BYTES;
#pragma unroll
        for (int it = 0; it < 4; it++) {
            int idx = it * 256 + tid;
            int kr = idx >> 5, nq = idx & 31;
            CP16(bb + kr * 544 + nq * 16, W2 + (size_t)(k0 + kr) * D_DIM + nq * 4);
        }
        CP_COMMIT();
    };

    issue(0, 0);
    issue(1, 1);

    int g = lane >> 2, t = lane & 3;
    int m0w = (wid & 1) * 64, n0w = (wid >> 1) * 32;

    float c[4][4][4];
#pragma unroll
    for (int a = 0; a < 4; a++)
#pragma unroll
        for (int b = 0; b < 4; b++)
#pragma unroll
            for (int r = 0; r < 4; r++) c[a][b][r] = 0.f;

    const int NCH = F_DIM / 32;  // 64
    int cur = 0, ibuf = 2;
    for (int ci = 0; ci < NCH; ci++) {
        CP_WAIT1();
        __syncthreads();
        if (ci + 2 < NCH) issue(ci + 2, ibuf); else CP_COMMIT();
        if (++ibuf == 3) ibuf = 0;

        const float* As = (const float*)(smem + 1024 + cur * (A_BYTES + B_BYTES));
        const float* Bs = As + A_BYTES / 4;
        if (++cur == 3) cur = 0;

#pragma unroll
        for (int kk = 0; kk < 4; kk++) {
            uint32_t af[4][4], bf[4][2];
#pragma unroll
            for (int mf = 0; mf < 4; mf++) {
                const float* ap = As + (m0w + mf * 16 + g) * AST + kk * 8 + t;
                af[mf][0] = __float_as_uint(ap[0]);
                af[mf][1] = __float_as_uint(ap[8 * AST]);
                af[mf][2] = __float_as_uint(ap[4]);
                af[mf][3] = __float_as_uint(ap[8 * AST + 4]);
            }
#pragma unroll
            for (int nf = 0; nf < 4; nf++) {
                const float* bp = Bs + (kk * 8 + t) * BST + n0w + nf * 8 + g;
                bf[nf][0] = __float_as_uint(bp[0]);
                bf[nf][1] = __float_as_uint(bp[4 * BST]);
            }
#pragma unroll
            for (int mf = 0; mf < 4; mf++)
#pragma unroll
                for (int nf = 0; nf < 4; nf++)
                    MMA_TF32(c[mf][nf], af[mf], bf[nf]);
        }
    }

#pragma unroll
    for (int mf = 0; mf < 4; mf++) {
#pragma unroll
        for (int half = 0; half < 2; half++) {
            int row = m0w + mf * 16 + g + 8 * half;
            if (m0 + row >= n_e) continue;
            float* yp = g_Y + (size_t)slots[row] * D_DIM + n0;
#pragma unroll
            for (int nf = 0; nf < 4; nf++) {
                float2 o;
                o.x = c[mf][nf][2 * half + 0];
                o.y = c[mf][nf][2 * half + 1];
                *(float2*)(yp + n0w + nf * 8 + 2 * t) = o;
            }
        }
    }
}

// ---------------- combine ----------------
__global__ void __launch_bounds__(256) combine_kernel(float* __restrict__ out) {
    int idx = blockIdx.x * 256 + threadIdx.x;
    int t   = idx / (D_DIM / 4);
    int d4  = idx % (D_DIM / 4);
    float p0 = g_probs[2 * t], p1 = g_probs[2 * t + 1];
    const float4* y0 = (const float4*)(g_Y + (size_t)(2 * t) * D_DIM) + d4;
    const float4* y1 = (const float4*)(g_Y + (size_t)(2 * t + 1) * D_DIM) + d4;
    float4 a = *y0, b = *y1, o;
    o.x = p0 * a.x + p1 * b.x;
    o.y = p0 * a.y + p1 * b.y;
    o.z = p0 * a.z + p1 * b.z;
    o.w = p0 * a.w + p1 * b.w;
    *((float4*)(out + (size_t)t * D_DIM) + d4) = o;
}

// ---------------- launch ----------------
extern "C" void kernel_launch(void* const* d_in, const int* in_sizes, int n_in,
                              void* d_out, int out_size) {
    const float* x  = (const float*)d_in[0];
    const float* wg = (const float*)d_in[1];
    const float* w1 = (const float*)d_in[2];
    const float* w3 = (const float*)d_in[3];
    const float* w2 = (const float*)d_in[4];
    float* out = (float*)d_out;

    const int SMEM1 = 1024 + 3 * (A_BYTES + 2 * B_BYTES);  // 160768
    const int SMEM2 = 1024 + 3 * (A_BYTES + B_BYTES);      // 108544
    static int configured = 0;
    cudaFuncSetAttribute(gemm1_kernel, cudaFuncAttributeMaxDynamicSharedMemorySize, SMEM1);
    cudaFuncSetAttribute(gemm2_kernel, cudaFuncAttributeMaxDynamicSharedMemorySize, SMEM2);
    (void)configured;

    float *xr, *w1r, *w3r, *w2r;
    cudaGetSymbolAddress((void**)&xr,  g_xr);
    cudaGetSymbolAddress((void**)&w1r, g_w1r);
    cudaGetSymbolAddress((void**)&w3r, g_w3r);
    cudaGetSymbolAddress((void**)&w2r, g_w2r);

    init_kernel<<<1, 32>>>();
    round_kernel<<<2048, 256>>>((const float4*)x,  (float4*)xr,  T_TOK * D_DIM / 4);
    round_kernel<<<4096, 256>>>((const float4*)w1, (float4*)w1r, E_EXP * D_DIM * F_DIM / 4);
    round_kernel<<<4096, 256>>>((const float4*)w3, (float4*)w3r, E_EXP * D_DIM * F_DIM / 4);
    round_kernel<<<4096, 256>>>((const float4*)w2, (float4*)w2r, E_EXP * F_DIM * D_DIM / 4);
    gate_kernel<<<T_TOK / 8, 256>>>(x, wg);

    gemm1_kernel<<<dim3(T_TOK / 128, F_DIM / 128, E_EXP), 256, SMEM1>>>(xr, w1r, w3r);
    gemm2_kernel<<<dim3(T_TOK / 128, D_DIM / 128, E_EXP), 256, SMEM2>>>(w2r);
    combine_kernel<<<(T_TOK * D_DIM / 4) / 256, 256>>>(out);
}